// round 4
// baseline (speedup 1.0000x reference)
#include <cuda_runtime.h>
#include <cuda_bf16.h>
#include <cstdint>
#include <math.h>

#define NN 10000
#define EE 160000
#define TT 12
#define FF 256
#define K_FULL 1024
#define K_HALF 512
#define NOUT 512

// ---------------- weight storage offsets (elements) ----------------
#define W_ENC0 0
#define W_ENC1 (512 * 1024)
#define W_DEC0 (2 * 512 * 1024)
#define W_DEC1 (2 * 512 * 1024 + 512 * 512)
#define W_OUTP (W_DEC1 + 512 * 1024)
#define W_TOTAL (W_OUTP + 256 * 256)

__device__ __align__(16) __nv_bfloat16 g_inh[NN * K_FULL];
__device__ __align__(16) __nv_bfloat16 g_inl[NN * K_FULL];
__device__ float         g_h0[NN * FF];
__device__ float         g_h1[NN * FF];
__device__ __align__(16) __nv_bfloat16 g_h1h[NN * FF];
__device__ __align__(16) __nv_bfloat16 g_h1l[NN * FF];
__device__ __align__(16) __nv_bfloat16 g_Wh[W_TOTAL];
__device__ __align__(16) __nv_bfloat16 g_Wl[W_TOTAL];
__device__ float         g_bias[4 * NOUT + FF];
__device__ int           g_deg[NN];
__device__ int           g_rowptr[NN + 1];
__device__ int           g_cursor[NN];
__device__ int           g_col[EE];
__device__ float         g_deginv[NN];

// ---------------- small helpers ----------------
__device__ __forceinline__ uint32_t smem_u32(const void* p) {
    uint32_t a;
    asm("{ .reg .u64 t; cvta.to.shared.u64 t, %1; cvt.u32.u64 %0, t; }" : "=r"(a) : "l"(p));
    return a;
}
__device__ __forceinline__ void ldsm_x4(uint32_t* r, uint32_t addr) {
    asm volatile("ldmatrix.sync.aligned.m8n8.x4.shared.b16 {%0,%1,%2,%3}, [%4];"
                 : "=r"(r[0]), "=r"(r[1]), "=r"(r[2]), "=r"(r[3]) : "r"(addr));
}
__device__ __forceinline__ void ldsm_x2(uint32_t* r, uint32_t addr) {
    asm volatile("ldmatrix.sync.aligned.m8n8.x2.shared.b16 {%0,%1}, [%2];"
                 : "=r"(r[0]), "=r"(r[1]) : "r"(addr));
}
__device__ __forceinline__ void mma_bf16(float* c, const uint32_t* a, const uint32_t* b) {
    asm volatile("mma.sync.aligned.m16n8k16.row.col.f32.bf16.bf16.f32 "
                 "{%0,%1,%2,%3}, {%4,%5,%6,%7}, {%8,%9}, {%0,%1,%2,%3};"
                 : "+f"(c[0]), "+f"(c[1]), "+f"(c[2]), "+f"(c[3])
                 : "r"(a[0]), "r"(a[1]), "r"(a[2]), "r"(a[3]), "r"(b[0]), "r"(b[1]));
}
__device__ __forceinline__ void cp16(uint32_t d, const void* s) {
    asm volatile("cp.async.cg.shared.global [%0], [%1], 16;" :: "r"(d), "l"(s));
}
__device__ __forceinline__ void cp_commit() {
    asm volatile("cp.async.commit_group;" ::: "memory");
}
__device__ __forceinline__ void cp_wait2() {
    asm volatile("cp.async.wait_group 2;" ::: "memory");
}
// pack 2 floats -> bf16x2 word (hi parts)
__device__ __forceinline__ uint32_t pk_hi(float a, float b, float& ra, float& rb) {
    __nv_bfloat16 ha = __float2bfloat16_rn(a);
    __nv_bfloat16 hb = __float2bfloat16_rn(b);
    ra = a - __bfloat162float(ha);
    rb = b - __bfloat162float(hb);
    return (uint32_t)__bfloat16_as_ushort(ha) | ((uint32_t)__bfloat16_as_ushort(hb) << 16);
}
__device__ __forceinline__ uint32_t pk(float a, float b) {
    return (uint32_t)__bfloat16_as_ushort(__float2bfloat16_rn(a)) |
           ((uint32_t)__bfloat16_as_ushort(__float2bfloat16_rn(b)) << 16);
}
// write float4 as bf16 hi/lo (4+4 halfs = 8B each)
__device__ __forceinline__ void store_split4(__nv_bfloat16* bh, __nv_bfloat16* bl,
                                             size_t idx, float4 v) {
    float r0, r1, r2, r3;
    uint32_t h0 = pk_hi(v.x, v.y, r0, r1);
    uint32_t h1 = pk_hi(v.z, v.w, r2, r3);
    *(uint2*)(bh + idx) = make_uint2(h0, h1);
    *(uint2*)(bl + idx) = make_uint2(pk(r0, r1), pk(r2, r3));
}

// ---------------- setup kernels ----------------
__global__ void k_zero_int(int* p, int n) {
    int i = blockIdx.x * blockDim.x + threadIdx.x;
    if (i < n) p[i] = 0;
}
__global__ void k_zero_f(float* p, int n) {
    int i = blockIdx.x * blockDim.x + threadIdx.x;
    if (i < n) p[i] = 0.0f;
}
__global__ void k_count_deg(const int* __restrict__ dst) {
    int e = blockIdx.x * blockDim.x + threadIdx.x;
    if (e < EE) atomicAdd(&g_deg[dst[e]], 1);
}
__global__ void k_scan_deg() {
    __shared__ int partial[256];
    int t = threadIdx.x;
    const int CH = (NN + 255) / 256;
    int base = t * CH;
    int s = 0;
    for (int i = 0; i < CH; i++) {
        int idx = base + i;
        if (idx < NN) s += g_deg[idx];
    }
    partial[t] = s;
    __syncthreads();
    if (t == 0) {
        int run = 0;
        for (int i = 0; i < 256; i++) { int v = partial[i]; partial[i] = run; run += v; }
        g_rowptr[NN] = run;
    }
    __syncthreads();
    int run = partial[t];
    for (int i = 0; i < CH; i++) {
        int idx = base + i;
        if (idx < NN) {
            g_rowptr[idx] = run;
            g_cursor[idx] = run;
            int d = g_deg[idx];
            g_deginv[idx] = (d > 0) ? (1.0f / (float)d) : 0.0f;
            run += d;
        }
    }
}
__global__ void k_fill_csr(const int* __restrict__ src, const int* __restrict__ dst) {
    int e = blockIdx.x * blockDim.x + threadIdx.x;
    if (e < EE) {
        int p = atomicAdd(&g_cursor[dst[e]], 1);
        g_col[p] = src[e];
    }
}

// pack GRU weights -> [N,K] K-major bf16 hi/lo, u/c columns interleaved.
__global__ void k_pack_gru(const float* __restrict__ Wxs, const float* __restrict__ Wxn,
                           const float* __restrict__ Whs, const float* __restrict__ Whn,
                           const float* __restrict__ bx, const float* __restrict__ bh,
                           __nv_bfloat16* __restrict__ Wh, __nv_bfloat16* __restrict__ Wl,
                           float* __restrict__ bias, int full) {
    int K = full ? K_FULL : K_HALF;
    int j = blockIdx.x * blockDim.x + threadIdx.x;
    if (j >= NOUT * K) return;
    int n = j / K, k = j % K;
    int f = n >> 1;
    int col = (n & 1) ? (2 * FF + f) : (FF + f);
    int blk = k >> 8, r = k & (FF - 1);
    const float* srcW;
    if (full) srcW = (blk == 0) ? Wxs : (blk == 1) ? Wxn : (blk == 2) ? Whs : Whn;
    else      srcW = (blk == 0) ? Whs : Whn;
    float w = srcW[r * (3 * FF) + col];
    __nv_bfloat16 hi = __float2bfloat16_rn(w);
    Wh[j] = hi;
    Wl[j] = __float2bfloat16_rn(w - __bfloat162float(hi));
    if (k == 0) bias[n] = bx[col] + bh[col];
}
__global__ void k_pack_out(const float* __restrict__ W, const float* __restrict__ b,
                           __nv_bfloat16* __restrict__ Wh, __nv_bfloat16* __restrict__ Wl,
                           float* __restrict__ bias) {
    int j = blockIdx.x * blockDim.x + threadIdx.x;
    if (j >= FF * FF) return;
    int n = j / FF, k = j % FF;
    float w = W[k * FF + n];
    __nv_bfloat16 hi = __float2bfloat16_rn(w);
    Wh[j] = hi;
    Wl[j] = __float2bfloat16_rn(w - __bfloat162float(hi));
    if (k == 0) bias[n] = b[n];
}

// ---------------- aggregation (writes pre-split bf16 A rows) ----------------
__device__ __forceinline__ float4 f4add(float4 a, float4 b) {
    return make_float4(a.x + b.x, a.y + b.y, a.z + b.z, a.w + b.w);
}
__device__ __forceinline__ float4 f4scale(float4 a, float s) {
    return make_float4(a.x * s, a.y * s, a.z * s, a.w * s);
}
// row = [ x | mean_nbr x | h | mean_nbr h ], stride 1024
__global__ void k_agg_full(const float* __restrict__ x, const float* __restrict__ h) {
    int node = blockIdx.x;
    int t = threadIdx.x;  // 64
    int beg = g_rowptr[node], end = g_rowptr[node + 1];
    float4 sx = make_float4(0, 0, 0, 0), sh = sx;
    for (int j = beg; j < end; j++) {
        int s = g_col[j];
        sx = f4add(sx, *(const float4*)&x[(size_t)s * FF + t * 4]);
        sh = f4add(sh, *(const float4*)&h[(size_t)s * FF + t * 4]);
    }
    float di = g_deginv[node];
    size_t base = (size_t)node * K_FULL;
    store_split4(g_inh, g_inl, base + t * 4,       *(const float4*)&x[(size_t)node * FF + t * 4]);
    store_split4(g_inh, g_inl, base + 256 + t * 4, f4scale(sx, di));
    store_split4(g_inh, g_inl, base + 512 + t * 4, *(const float4*)&h[(size_t)node * FF + t * 4]);
    store_split4(g_inh, g_inl, base + 768 + t * 4, f4scale(sh, di));
}
// row = [ h | mean_nbr h ], stride 512
__global__ void k_agg_h(const float* __restrict__ h) {
    int node = blockIdx.x;
    int t = threadIdx.x;
    int beg = g_rowptr[node], end = g_rowptr[node + 1];
    float4 sh = make_float4(0, 0, 0, 0);
    for (int j = beg; j < end; j++)
        sh = f4add(sh, *(const float4*)&h[(size_t)g_col[j] * FF + t * 4]);
    size_t base = (size_t)node * K_HALF;
    store_split4(g_inh, g_inl, base + t * 4,       *(const float4*)&h[(size_t)node * FF + t * 4]);
    store_split4(g_inh, g_inl, base + 256 + t * 4, f4scale(sh, g_deginv[node]));
}

// ---------------- cp.async 4-stage mma.sync bf16-split GEMM ----------------
// C[M,N] = A[M,K] @ W[K,N], A pre-split bf16 hi/lo (row stride K), W pre-split [N,K].
// 3 passes: Ah*Bh + Al*Bh + Ah*Bl.
// mode 0: fused GRU epilogue (u/c interleaved), Hout = hidden [NN,FF];
//         optional bf16 split mirror of new h (outh/outl) for downstream GEMM input.
// mode 1: bias epilogue, Hout = output rows [NN,FF]
#define BM 128
#define BN 128
#define BK 32
#define PAD 40                               // halfs per smem row (80 B)
#define SUB_BYTES (128 * 80)                 // one 128x32 tile
#define STAGE_BYTES (4 * SUB_BYTES)          // Ah, Al, Wh, Wl
#define NSTG 4
#define SMEM_BYTES (NSTG * STAGE_BYTES)      // 163840

__global__ __launch_bounds__(256, 1) void k_mma_gemm(
    const __nv_bfloat16* __restrict__ Ah, const __nv_bfloat16* __restrict__ Al, int K,
    const __nv_bfloat16* __restrict__ Wh, const __nv_bfloat16* __restrict__ Wl,
    const float* __restrict__ bias,
    float* __restrict__ Hout,
    __nv_bfloat16* __restrict__ outh, __nv_bfloat16* __restrict__ outl,
    int mode) {
    extern __shared__ __align__(16) char smem[];
    const uint32_t sbase = smem_u32(smem);

    const int tid = threadIdx.x;
    const int lane = tid & 31;
    const int wid = tid >> 5;
    const int wm = wid & 1;
    const int wn = wid >> 1;
    const int bm = blockIdx.y * BM;
    const int bn = blockIdx.x * BN;

    // cp.async loader: thread -> row = tid>>1, two 16B segs
    const int lr = tid >> 1;
    const int ls = (tid & 1) * 2;
    int gmld = bm + lr; if (gmld >= NN) gmld = NN - 1;
    const __nv_bfloat16* a_h = Ah + (size_t)gmld * K;
    const __nv_bfloat16* a_l = Al + (size_t)gmld * K;
    const __nv_bfloat16* w_h = Wh + (size_t)(bn + lr) * K;
    const __nv_bfloat16* w_l = Wl + (size_t)(bn + lr) * K;
    const uint32_t srow = lr * 80;

    auto issue = [&](int c) {
        uint32_t st = sbase + (c & (NSTG - 1)) * STAGE_BYTES + srow;
        int k0 = c * BK;
#pragma unroll
        for (int k = 0; k < 2; k++) {
            int seg = ls + k;
            uint32_t o = seg * 16;
            const int go = k0 + seg * 8;
            cp16(st + 0 * SUB_BYTES + o, a_h + go);
            cp16(st + 1 * SUB_BYTES + o, a_l + go);
            cp16(st + 2 * SUB_BYTES + o, w_h + go);
            cp16(st + 3 * SUB_BYTES + o, w_l + go);
        }
        cp_commit();
    };

    // ldmatrix per-lane address components
    const int aRowL = (lane & 15);
    const int aSegB = (lane >> 4) * 16;      // bytes
    const int bIdx  = lane & 15;
    const int bRowL = bIdx & 7;
    const int bSegB = (bIdx >> 3) * 16;      // bytes

    float acc[4][4][4];
#pragma unroll
    for (int i = 0; i < 4; i++)
#pragma unroll
        for (int j = 0; j < 4; j++)
#pragma unroll
            for (int q = 0; q < 4; q++) acc[i][j][q] = 0.0f;

    auto compute = [&](int s) {
        uint32_t base = sbase + s * STAGE_BYTES;
#pragma unroll
        for (int kk = 0; kk < 2; kk++) {
            uint32_t ah[4][4], al[4][4];
#pragma unroll
            for (int i = 0; i < 4; i++) {
                uint32_t off = (uint32_t)(wm * 64 + i * 16 + aRowL) * 80 + kk * 32 + aSegB;
                ldsm_x4(ah[i], base + 0 * SUB_BYTES + off);
                ldsm_x4(al[i], base + 1 * SUB_BYTES + off);
            }
            uint32_t bh[4][2], bl[4][2];
#pragma unroll
            for (int j = 0; j < 4; j++) {
                uint32_t off = (uint32_t)(wn * 32 + j * 8 + bRowL) * 80 + kk * 32 + bSegB;
                ldsm_x2(bh[j], base + 2 * SUB_BYTES + off);
                ldsm_x2(bl[j], base + 3 * SUB_BYTES + off);
            }
#pragma unroll
            for (int i = 0; i < 4; i++)
#pragma unroll
                for (int j = 0; j < 4; j++) {
                    mma_bf16(acc[i][j], ah[i], bh[j]);
                    mma_bf16(acc[i][j], al[i], bh[j]);
                    mma_bf16(acc[i][j], ah[i], bl[j]);
                }
        }
    };

    const int NC = K / BK;   // >= 8 always
    issue(0); issue(1); issue(2);
    for (int c = 0; c < NC; c++) {
        cp_wait2();
        __syncthreads();
        if (c + 3 < NC) issue(c + 3); else cp_commit();
        compute(c & (NSTG - 1));
    }

    // ---------------- epilogue ----------------
#pragma unroll
    for (int i = 0; i < 4; i++) {
        int r0 = bm + wm * 64 + i * 16 + (lane >> 2);
#pragma unroll
        for (int j = 0; j < 4; j++) {
            int gcol = bn + wn * 32 + j * 8 + (lane & 3) * 2;
            float b0 = __ldg(&bias[gcol]);
            float b1 = __ldg(&bias[gcol + 1]);
            if (mode == 0) {
                int f = gcol >> 1;
#pragma unroll
                for (int half = 0; half < 2; half++) {
                    int gm = r0 + half * 8;
                    if (gm < NN) {
                        float zu = acc[i][j][half * 2]     + b0;
                        float zc = acc[i][j][half * 2 + 1] + b1;
                        float u = 1.0f / (1.0f + __expf(-zu));
                        float cc = tanhf(zc);
                        float hv = Hout[(size_t)gm * FF + f];
                        float nh = u * hv + (1.0f - u) * cc;
                        Hout[(size_t)gm * FF + f] = nh;
                        if (outh) {
                            __nv_bfloat16 hh = __float2bfloat16_rn(nh);
                            outh[(size_t)gm * FF + f] = hh;
                            outl[(size_t)gm * FF + f] =
                                __float2bfloat16_rn(nh - __bfloat162float(hh));
                        }
                    }
                }
            } else {
#pragma unroll
                for (int half = 0; half < 2; half++) {
                    int gm = r0 + half * 8;
                    if (gm < NN) {
                        float2 v;
                        v.x = acc[i][j][half * 2]     + b0;
                        v.y = acc[i][j][half * 2 + 1] + b1;
                        *(float2*)&Hout[(size_t)gm * FF + gcol] = v;
                    }
                }
            }
        }
    }
}

// ---------------- host orchestration ----------------
extern "C" void kernel_launch(void* const* d_in, const int* in_sizes, int n_in,
                              void* d_out, int out_size) {
    const float* x    = (const float*)d_in[0];
    const int*   src  = (const int*)d_in[1];
    const int*   dst  = (const int*)d_in[2];
    const float* eWxs = (const float*)d_in[3];
    const float* eWxn = (const float*)d_in[4];
    const float* ebx  = (const float*)d_in[5];
    const float* eWhs = (const float*)d_in[6];
    const float* eWhn = (const float*)d_in[7];
    const float* ebh  = (const float*)d_in[8];
    const float* dWxs = (const float*)d_in[9];
    const float* dWxn = (const float*)d_in[10];
    const float* dbx  = (const float*)d_in[11];
    const float* dWhs = (const float*)d_in[12];
    const float* dWhn = (const float*)d_in[13];
    const float* dbh  = (const float*)d_in[14];
    const float* outW = (const float*)d_in[15];
    const float* outB = (const float*)d_in[16];
    float* out = (float*)d_out;

    float *p_h0, *p_h1, *p_bias;
    __nv_bfloat16 *p_inh, *p_inl, *p_Wh, *p_Wl, *p_h1h, *p_h1l;
    int* p_deg;
    cudaGetSymbolAddress((void**)&p_inh, g_inh);
    cudaGetSymbolAddress((void**)&p_inl, g_inl);
    cudaGetSymbolAddress((void**)&p_h0, g_h0);
    cudaGetSymbolAddress((void**)&p_h1, g_h1);
    cudaGetSymbolAddress((void**)&p_h1h, g_h1h);
    cudaGetSymbolAddress((void**)&p_h1l, g_h1l);
    cudaGetSymbolAddress((void**)&p_Wh, g_Wh);
    cudaGetSymbolAddress((void**)&p_Wl, g_Wl);
    cudaGetSymbolAddress((void**)&p_bias, g_bias);
    cudaGetSymbolAddress((void**)&p_deg, g_deg);

    cudaFuncSetAttribute(k_mma_gemm, cudaFuncAttributeMaxDynamicSharedMemorySize, SMEM_BYTES);

    const int WLF = FF * 3 * FF;
    const int BLF = 3 * FF;

    // graph structure
    k_zero_int<<<(NN + 255) / 256, 256>>>(p_deg, NN);
    k_count_deg<<<(EE + 255) / 256, 256>>>(dst);
    k_scan_deg<<<1, 256>>>();
    k_fill_csr<<<(EE + 255) / 256, 256>>>(src, dst);

    // zero hidden
    k_zero_f<<<(NN * FF + 255) / 256, 256>>>(p_h0, NN * FF);
    k_zero_f<<<(NN * FF + 255) / 256, 256>>>(p_h1, NN * FF);

    // pack + split weights
    {
        int nfull = NOUT * K_FULL, nhalf = NOUT * K_HALF;
        k_pack_gru<<<(nfull + 255) / 256, 256>>>(eWxs, eWxn, eWhs, eWhn, ebx, ebh,
                                                 p_Wh + W_ENC0, p_Wl + W_ENC0, p_bias + 0 * NOUT, 1);
        k_pack_gru<<<(nfull + 255) / 256, 256>>>(eWxs + WLF, eWxn + WLF, eWhs + WLF, eWhn + WLF,
                                                 ebx + BLF, ebh + BLF,
                                                 p_Wh + W_ENC1, p_Wl + W_ENC1, p_bias + 1 * NOUT, 1);
        k_pack_gru<<<(nhalf + 255) / 256, 256>>>(dWxs, dWxn, dWhs, dWhn, dbx, dbh,
                                                 p_Wh + W_DEC0, p_Wl + W_DEC0, p_bias + 2 * NOUT, 0);
        k_pack_gru<<<(nfull + 255) / 256, 256>>>(dWxs + WLF, dWxn + WLF, dWhs + WLF, dWhn + WLF,
                                                 dbx + BLF, dbh + BLF,
                                                 p_Wh + W_DEC1, p_Wl + W_DEC1, p_bias + 3 * NOUT, 1);
        k_pack_out<<<(FF * FF + 255) / 256, 256>>>(outW, outB, p_Wh + W_OUTP, p_Wl + W_OUTP,
                                                   p_bias + 4 * NOUT);
    }

    dim3 grid_pre(NOUT / BN, (NN + BM - 1) / BM);   // (4, 79)
    dim3 grid_out(FF / BN, (NN + BM - 1) / BM);     // (2, 79)

    // encoder
    for (int t = 0; t < TT; t++) {
        k_agg_full<<<NN, 64>>>(x + (size_t)t * NN * FF, p_h0);
        k_mma_gemm<<<grid_pre, 256, SMEM_BYTES>>>(p_inh, p_inl, K_FULL,
                                                  p_Wh + W_ENC0, p_Wl + W_ENC0,
                                                  p_bias + 0 * NOUT, p_h0, nullptr, nullptr, 0);
        k_agg_full<<<NN, 64>>>(p_h0, p_h1);
        k_mma_gemm<<<grid_pre, 256, SMEM_BYTES>>>(p_inh, p_inl, K_FULL,
                                                  p_Wh + W_ENC1, p_Wl + W_ENC1,
                                                  p_bias + 1 * NOUT, p_h1, nullptr, nullptr, 0);
    }
    // decoder
    for (int t = 0; t < TT; t++) {
        k_agg_h<<<NN, 64>>>(p_h0);
        k_mma_gemm<<<grid_pre, 256, SMEM_BYTES>>>(p_inh, p_inl, K_HALF,
                                                  p_Wh + W_DEC0, p_Wl + W_DEC0,
                                                  p_bias + 2 * NOUT, p_h0, nullptr, nullptr, 0);
        k_agg_full<<<NN, 64>>>(p_h0, p_h1);
        k_mma_gemm<<<grid_pre, 256, SMEM_BYTES>>>(p_inh, p_inl, K_FULL,
                                                  p_Wh + W_DEC1, p_Wl + W_DEC1,
                                                  p_bias + 3 * NOUT, p_h1, p_h1h, p_h1l, 0);
        k_mma_gemm<<<grid_out, 256, SMEM_BYTES>>>(p_h1h, p_h1l, FF,
                                                  p_Wh + W_OUTP, p_Wl + W_OUTP,
                                                  p_bias + 4 * NOUT, out + (size_t)t * NN * FF,
                                                  nullptr, nullptr, 1);
    }
    (void)in_sizes; (void)n_in; (void)out_size;
}